// round 1
// baseline (speedup 1.0000x reference)
#include <cuda_runtime.h>
#include <math_constants.h>

// Problem constants
#define K_CODES 1024
#define C_DIM   256
#define N_PIX   32768          // 32 * 32 * 32
#define ZQ_ELEMS 8388608       // 32*256*32*32

// Tiling
#define TM 32                  // pixels per block
#define TN 128                 // codes per k-chunk
#define CC 32                  // channels per c-chunk
#define NTHREADS 128           // 16 (tx over codes) x 8 (ty over pixels)

// Normalized codebook: row-major (for gather) and transposed (for GEMM loads)
__device__ float g_wn[K_CODES * C_DIM];   // [k][c]
__device__ float g_wt[C_DIM * K_CODES];   // [c][k]

// ---------------------------------------------------------------------------
// fp32x2 packed helpers (Blackwell FFMA2 — ptxas won't auto-fuse, PTX only)
// ---------------------------------------------------------------------------
__device__ __forceinline__ unsigned long long dupf(float x) {
    unsigned long long r;
    asm("mov.b64 %0, {%1, %1};" : "=l"(r) : "f"(x));
    return r;
}
__device__ __forceinline__ void ffma2(unsigned long long& d,
                                      unsigned long long a,
                                      unsigned long long b) {
    asm("fma.rn.f32x2 %0, %1, %2, %0;" : "+l"(d) : "l"(a), "l"(b));
}
__device__ __forceinline__ void unpack2(unsigned long long v, float& lo, float& hi) {
    asm("mov.b64 {%0, %1}, %2;" : "=f"(lo), "=f"(hi) : "l"(v));
}

// ---------------------------------------------------------------------------
// Kernel 1: L2-normalize codebook rows; write row-major + transposed copies.
// One block per code row, 256 threads (one per channel).
// ---------------------------------------------------------------------------
__global__ void vq_norm_weight_kernel(const float* __restrict__ w) {
    const int k = blockIdx.x;
    const int t = threadIdx.x;
    float v = w[k * C_DIM + t];
    float s = v * v;
    #pragma unroll
    for (int off = 16; off; off >>= 1)
        s += __shfl_xor_sync(0xffffffffu, s, off);
    __shared__ float ssum[8];
    if ((t & 31) == 0) ssum[t >> 5] = s;
    __syncthreads();
    float tot = ssum[0] + ssum[1] + ssum[2] + ssum[3]
              + ssum[4] + ssum[5] + ssum[6] + ssum[7];
    float nrm = sqrtf(tot);
    float den = fmaxf(nrm, 1e-12f);
    float o = v / den;                 // full-precision fp32 divide (match jnp)
    g_wn[k * C_DIM + t] = o;
    g_wt[t * K_CODES + k] = o;
}

// ---------------------------------------------------------------------------
// Kernel 2: per-pixel argmax over <z_n, w_k> + gather z_q.
// Grid: N_PIX/TM = 1024 blocks, 128 threads.
// Static shared exactly 48KB -> 4 blocks/SM, no attribute opt-in needed.
// ---------------------------------------------------------------------------
__global__ __launch_bounds__(NTHREADS)
void vq_argmax_kernel(const float* __restrict__ z,
                      float* __restrict__ out,
                      int write_idx) {
    __shared__ float zs[C_DIM * TM];   // [c][p], 32768 B
    __shared__ float ws[CC * TN];      // [c][k], 16384 B (reused as int idx buf)

    const int tid = threadIdx.x;
    const int tx = tid & 15;           // code-group lane
    const int ty = tid >> 4;           // pixel-group row
    const int n0 = blockIdx.x * TM;    // first pixel of tile (same b for all 32)
    const int b   = n0 >> 10;
    const int hw0 = n0 & 1023;
    const float* zbase = z + (((size_t)b * C_DIM) << 10) + hw0;

    // ---- Load z tile [TM pixels][C_DIM channels] into smem transposed ----
    #pragma unroll 4
    for (int i = tid; i < C_DIM * TM; i += NTHREADS) {
        int p = i & (TM - 1);
        int c = i >> 5;
        zs[c * TM + p] = zbase[((size_t)c << 10) + p];   // coalesced over p
    }

    // Running best per owned pixel (pixels ty*4 .. ty*4+3)
    float rbv[4];
    int   rbi[4];
    #pragma unroll
    for (int i = 0; i < 4; i++) { rbv[i] = -CUDART_INF_F; rbi[i] = 0; }

    for (int kc = 0; kc < K_CODES; kc += TN) {
        unsigned long long acc[4][4];   // [pixel][code-pair] fp32x2 accumulators
        #pragma unroll
        for (int i = 0; i < 4; i++)
            #pragma unroll
            for (int j = 0; j < 4; j++) acc[i][j] = 0ull;

        for (int cc = 0; cc < C_DIM; cc += CC) {
            __syncthreads();   // previous compute done before ws overwrite (also covers zs fill)
            // Load ws chunk [CC][TN] from transposed codebook, float4 coalesced
            #pragma unroll
            for (int i = tid; i < (CC * TN) / 4; i += NTHREADS) {
                int c  = i >> 5;        // 32 float4 per row of TN=128
                int k4 = i & 31;
                ((float4*)ws)[i] =
                    ((const float4*)(g_wt + (size_t)(cc + c) * K_CODES + kc))[k4];
            }
            __syncthreads();

            #pragma unroll 8
            for (int c = 0; c < CC; c++) {
                float4 zv = *(const float4*)&zs[(cc + c) * TM + (ty << 2)];
                ulonglong2 wq0 = *(const ulonglong2*)&ws[c * TN + (tx << 3)];
                ulonglong2 wq1 = *(const ulonglong2*)&ws[c * TN + (tx << 3) + 4];
                unsigned long long zp0 = dupf(zv.x);
                unsigned long long zp1 = dupf(zv.y);
                unsigned long long zp2 = dupf(zv.z);
                unsigned long long zp3 = dupf(zv.w);
                ffma2(acc[0][0], zp0, wq0.x); ffma2(acc[0][1], zp0, wq0.y);
                ffma2(acc[0][2], zp0, wq1.x); ffma2(acc[0][3], zp0, wq1.y);
                ffma2(acc[1][0], zp1, wq0.x); ffma2(acc[1][1], zp1, wq0.y);
                ffma2(acc[1][2], zp1, wq1.x); ffma2(acc[1][3], zp1, wq1.y);
                ffma2(acc[2][0], zp2, wq0.x); ffma2(acc[2][1], zp2, wq0.y);
                ffma2(acc[2][2], zp2, wq1.x); ffma2(acc[2][3], zp2, wq1.y);
                ffma2(acc[3][0], zp3, wq0.x); ffma2(acc[3][1], zp3, wq0.y);
                ffma2(acc[3][2], zp3, wq1.x); ffma2(acc[3][3], zp3, wq1.y);
            }
        }

        // ---- Chunk argmax: thread-local over 8 codes, then across 16 tx lanes ----
        #pragma unroll
        for (int i = 0; i < 4; i++) {
            float bv = -CUDART_INF_F;
            int   bk = 0;
            #pragma unroll
            for (int j = 0; j < 4; j++) {
                float lo, hi;
                unpack2(acc[i][j], lo, hi);
                int k0 = kc + (tx << 3) + (j << 1);
                if (lo > bv) { bv = lo; bk = k0; }       // strict >: first max wins
                if (hi > bv) { bv = hi; bk = k0 + 1; }
            }
            #pragma unroll
            for (int off = 8; off; off >>= 1) {          // reduce within 16-lane group
                float ov = __shfl_xor_sync(0xffffffffu, bv, off);
                int   ok = __shfl_xor_sync(0xffffffffu, bk, off);
                if (ov > bv || (ov == bv && ok < bk)) { bv = ov; bk = ok; }
            }
            // running best across k-chunks (later chunks have larger k; strict >)
            if (bv > rbv[i]) { rbv[i] = bv; rbi[i] = bk; }
        }
    }

    // ---- Publish per-pixel indices (reuse ws as int buffer) ----
    __syncthreads();
    int* sbidx = (int*)ws;
    if (tx == 0) {
        #pragma unroll
        for (int i = 0; i < 4; i++) sbidx[(ty << 2) + i] = rbi[i];
    }
    __syncthreads();

    // ---- Write z_q: out[b][c][h][w] = g_wn[idx[p]][c]; coalesced over p ----
    #pragma unroll 4
    for (int i = tid; i < C_DIM * TM; i += NTHREADS) {
        int p = i & (TM - 1);
        int c = i >> 5;
        out[(((size_t)(b * C_DIM + c)) << 10) + hw0 + p] =
            g_wn[(size_t)sbidx[p] * C_DIM + c];
    }
    // ---- Indices output (as float), after the z_q block ----
    if (write_idx && tid < TM) {
        out[ZQ_ELEMS + n0 + tid] = (float)sbidx[tid];
    }
}

// ---------------------------------------------------------------------------
extern "C" void kernel_launch(void* const* d_in, const int* in_sizes, int n_in,
                              void* d_out, int out_size) {
    const float* z_e    = (const float*)d_in[0];
    const float* weight = (const float*)d_in[1];
    float* out = (float*)d_out;

    const int write_idx = (out_size >= ZQ_ELEMS + N_PIX) ? 1 : 0;

    vq_norm_weight_kernel<<<K_CODES, C_DIM>>>(weight);
    vq_argmax_kernel<<<N_PIX / TM, NTHREADS>>>(z_e, out, write_idx);
}

// round 2
// speedup vs baseline: 1.6520x; 1.6520x over previous
#include <cuda_runtime.h>
#include <math_constants.h>

// Problem constants
#define K_CODES 1024
#define C_DIM   256
#define N_PIX   32768          // 32 * 32 * 32
#define ZQ_ELEMS 8388608       // 32*256*32*32

// Tiling
#define TM 64                  // pixels per block
#define TN 128                 // codes per k-chunk
#define CC 32                  // channels per c-chunk
#define NTHREADS 128           // 16 (tx over codes) x 8 (ty over pixels)
#define NSTAGES (8 * 8)        // 8 k-chunks x 8 c-chunks

// zs chunk: CC*TM floats = 8KB; ws chunk: CC*TN floats = 16KB; per stage 6144 floats
#define ZS_F   (CC * TM)       // 2048 floats
#define WS_F   (CC * TN)       // 4096 floats
#define STAGE_F (ZS_F + WS_F)  // 6144 floats = 24KB

// Normalized codebook: row-major (gather) and stage-packed (GEMM loads)
__device__ float g_wn[K_CODES * C_DIM];   // [k][c]
__device__ float g_wp[C_DIM * K_CODES];   // [(kcI*8+ccI)][c_in 32][k_in 128]

// ---------------------------------------------------------------------------
// fp32x2 packed helpers (Blackwell FFMA2 — PTX only, ptxas won't auto-fuse)
// ---------------------------------------------------------------------------
__device__ __forceinline__ unsigned long long dupf(float x) {
    unsigned long long r;
    asm("mov.b64 %0, {%1, %1};" : "=l"(r) : "f"(x));
    return r;
}
__device__ __forceinline__ void ffma2(unsigned long long& d,
                                      unsigned long long a,
                                      unsigned long long b) {
    asm("fma.rn.f32x2 %0, %1, %2, %0;" : "+l"(d) : "l"(a), "l"(b));
}
__device__ __forceinline__ void unpack2(unsigned long long v, float& lo, float& hi) {
    asm("mov.b64 {%0, %1}, %2;" : "=f"(lo), "=f"(hi) : "l"(v));
}
__device__ __forceinline__ unsigned int smem_u32(const void* p) {
    return (unsigned int)__cvta_generic_to_shared(p);
}
__device__ __forceinline__ void cp16(unsigned int dst, const void* src) {
    asm volatile("cp.async.cg.shared.global [%0], [%1], 16;" :: "r"(dst), "l"(src));
}
__device__ __forceinline__ void cp_commit() {
    asm volatile("cp.async.commit_group;");
}
template<int N>
__device__ __forceinline__ void cp_wait() {
    asm volatile("cp.async.wait_group %0;" :: "n"(N));
}

// ---------------------------------------------------------------------------
// Kernel 1: L2-normalize codebook rows; write row-major + stage-packed copies.
// ---------------------------------------------------------------------------
__global__ void vq_norm_weight_kernel(const float* __restrict__ w) {
    const int k = blockIdx.x;
    const int t = threadIdx.x;           // channel
    float v = w[k * C_DIM + t];
    float s = v * v;
    #pragma unroll
    for (int off = 16; off; off >>= 1)
        s += __shfl_xor_sync(0xffffffffu, s, off);
    __shared__ float ssum[8];
    if ((t & 31) == 0) ssum[t >> 5] = s;
    __syncthreads();
    float tot = ssum[0] + ssum[1] + ssum[2] + ssum[3]
              + ssum[4] + ssum[5] + ssum[6] + ssum[7];
    float den = fmaxf(sqrtf(tot), 1e-12f);
    float o = v / den;                   // full-precision fp32 divide (match jnp)
    g_wn[k * C_DIM + t] = o;
    // stage-packed: stage = (k>>7)*8 + (t>>5); within: [t&31][k&127]
    int stage = ((k >> 7) << 3) + (t >> 5);
    g_wp[(stage << 12) + ((t & 31) << 7) + (k & 127)] = o;
}

// ---------------------------------------------------------------------------
// Kernel 2: per-pixel argmax over <z_n, w_k> + gather z_q.
// Grid 512 blocks x 128 threads; 48KB static smem -> 4 blocks/SM.
// ---------------------------------------------------------------------------
__global__ __launch_bounds__(NTHREADS, 4)
void vq_argmax_kernel(const float* __restrict__ z,
                      float* __restrict__ out,
                      int write_idx) {
    __shared__ float sbuf[2][STAGE_F];   // 2 x 24KB = 48KB

    const int tid = threadIdx.x;
    const int tx = tid & 15;             // code lane (16)
    const int ty = tid >> 4;             // pixel row (8) -> pixels ty*8..ty*8+7
    const int n0 = blockIdx.x * TM;
    const int b   = n0 >> 10;
    const int hw0 = n0 & 1023;
    const float* zbase = z + (((size_t)b * C_DIM) << 10) + hw0;

    // ---- stage fill via cp.async (all linear 16B copies) ----
    auto fill = [&](int s) {
        float* buf = sbuf[s & 1];
        const int kcI = s >> 3, ccI = s & 7;
        // zs: [c 32][p 64] from z[b][ccI*32+c][hw0+p]
        #pragma unroll
        for (int t = 0; t < 4; t++) {
            int i  = tid + t * NTHREADS;         // float4 index, 512 total
            int c  = i >> 4;
            int p4 = i & 15;
            cp16(smem_u32(buf + i * 4),
                 zbase + (((size_t)(ccI * CC + c)) << 10) + p4 * 4);
        }
        // ws: 16KB linear from stage-packed codebook
        const float* wsrc = g_wp + ((size_t)s << 12);
        #pragma unroll
        for (int t = 0; t < 8; t++) {
            int i = tid + t * NTHREADS;          // float4 index, 1024 total
            cp16(smem_u32(buf + ZS_F + i * 4), wsrc + i * 4);
        }
        cp_commit();
    };

    fill(0);

    float rbv[8];
    int   rbi[8];
    #pragma unroll
    for (int i = 0; i < 8; i++) { rbv[i] = -CUDART_INF_F; rbi[i] = 0; }

    int s = 0;
    for (int kcI = 0; kcI < 8; kcI++) {
        unsigned long long acc[8][4];
        #pragma unroll
        for (int i = 0; i < 8; i++)
            #pragma unroll
            for (int j = 0; j < 4; j++) acc[i][j] = 0ull;

        for (int ccI = 0; ccI < 8; ccI++, s++) {
            if (s + 1 < NSTAGES) { fill(s + 1); cp_wait<1>(); }
            else                 { cp_wait<0>(); }
            __syncthreads();

            const float* zb = sbuf[s & 1];
            const float* wb = sbuf[s & 1] + ZS_F;

            #pragma unroll 4
            for (int c = 0; c < CC; c++) {
                const float* zr = zb + c * TM + (ty << 3);
                float4 za = *(const float4*)zr;
                float4 zc = *(const float4*)(zr + 4);
                const float* wr = wb + c * TN + (tx << 2);
                ulonglong2 w0 = *(const ulonglong2*)wr;         // codes tx*4..+3
                ulonglong2 w1 = *(const ulonglong2*)(wr + 64);  // codes 64+tx*4..+3
                unsigned long long zp[8];
                zp[0] = dupf(za.x); zp[1] = dupf(za.y);
                zp[2] = dupf(za.z); zp[3] = dupf(za.w);
                zp[4] = dupf(zc.x); zp[5] = dupf(zc.y);
                zp[6] = dupf(zc.z); zp[7] = dupf(zc.w);
                #pragma unroll
                for (int i = 0; i < 8; i++) {
                    ffma2(acc[i][0], zp[i], w0.x);
                    ffma2(acc[i][1], zp[i], w0.y);
                    ffma2(acc[i][2], zp[i], w1.x);
                    ffma2(acc[i][3], zp[i], w1.y);
                }
            }
            __syncthreads();   // compute done before next fill overwrites other buf
        }

        // ---- chunk argmax: local over 8 codes (increasing k), then 16 tx lanes ----
        const int kc = kcI * TN;
        #pragma unroll
        for (int i = 0; i < 8; i++) {
            float bv = -CUDART_INF_F;
            int   bk = 0;
            #pragma unroll
            for (int j = 0; j < 4; j++) {
                float lo, hi;
                unpack2(acc[i][j], lo, hi);
                int k0 = kc + (tx << 2) + ((j >> 1) << 6) + ((j & 1) << 1);
                if (lo > bv) { bv = lo; bk = k0; }
                if (hi > bv) { bv = hi; bk = k0 + 1; }
            }
            #pragma unroll
            for (int off = 8; off; off >>= 1) {
                float ov = __shfl_xor_sync(0xffffffffu, bv, off);
                int   ok = __shfl_xor_sync(0xffffffffu, bk, off);
                if (ov > bv || (ov == bv && ok < bk)) { bv = ov; bk = ok; }
            }
            if (bv > rbv[i]) { rbv[i] = bv; rbi[i] = bk; }  // later kc strictly >
        }
    }

    // ---- publish per-pixel indices ----
    __syncthreads();          // all compute (reads of sbuf) done
    int* sbidx = (int*)sbuf;
    if (tx == 0) {
        #pragma unroll
        for (int i = 0; i < 8; i++) sbidx[(ty << 3) + i] = rbi[i];
    }
    __syncthreads();

    // ---- write z_q: out[b][c][hw0+p] = g_wn[idx[p]][c], coalesced over p ----
    #pragma unroll 4
    for (int i = tid; i < C_DIM * TM; i += NTHREADS) {
        int p = i & (TM - 1);
        int c = i >> 6;
        out[(((size_t)(b * C_DIM + c)) << 10) + hw0 + p] =
            g_wn[(size_t)sbidx[p] * C_DIM + c];
    }
    // ---- indices output (as float), after the z_q block ----
    if (write_idx && tid < TM) {
        out[ZQ_ELEMS + n0 + tid] = (float)sbidx[tid];
    }
}

// ---------------------------------------------------------------------------
extern "C" void kernel_launch(void* const* d_in, const int* in_sizes, int n_in,
                              void* d_out, int out_size) {
    const float* z_e    = (const float*)d_in[0];
    const float* weight = (const float*)d_in[1];
    float* out = (float*)d_out;

    const int write_idx = (out_size >= ZQ_ELEMS + N_PIX) ? 1 : 0;

    vq_norm_weight_kernel<<<K_CODES, C_DIM>>>(weight);
    vq_argmax_kernel<<<N_PIX / TM, NTHREADS>>>(z_e, out, write_idx);
}